// round 2
// baseline (speedup 1.0000x reference)
#include <cuda_runtime.h>
#include <math.h>

// ---------------------------------------------------------------------------
// HistLoss: RGB-uv histogram Hellinger loss.
// B=4, C=3, H=W=256 -> N=65536 pixels. 128x128 bins, sigma=0.02, eps=1e-6.
//
// Structure:
//  k1_prep  : per-pixel logs -> a=logR-logG, b=logR-logB, Iy (both images)
//  k2_hist  : per (img,batch,pair,chunk) CTA: 128x128 outer-product
//             accumulation over its pixel chunk (register-tiled fp32 GEMM),
//             partial histogram to scratch. No atomics.
//  k3_reduce: sum 12 chunk-partials per unit -> hist; per-block sums for norm
//  k4_norm  : per (img,batch) normalization constants (fixed-order reduce)
//  k4_loss  : Hellinger partial sums over 96 blocks
//  k4_final : scalar loss
// ---------------------------------------------------------------------------

#define NPIX    65536
#define HB      128
#define CELLS   (HB*HB)
#define NBATCH  4
#define NUNITS  24          // 2 images * 4 batch * 3 pairings
#define NCHUNK  12
#define CHUNK_PX 5464       // multiple of 8; 12*5464 >= 65536
#define PIX     8           // pixels per barrier period in k2

static __device__ float g_a      [2*NBATCH*NPIX];
static __device__ float g_bdif   [2*NBATCH*NPIX];
static __device__ float g_iy     [2*NBATCH*NPIX];
static __device__ float g_partial[NUNITS*NCHUNK*CELLS];   // ~18.9 MB
static __device__ float g_hist   [NUNITS*CELLS];
static __device__ float g_blocksum[NUNITS*64];
static __device__ float g_norm   [8];                     // [img*4+batch]
static __device__ float g_losspart[96];

// -------------------------------------------------------------------- k1 ---
__global__ void k1_prep(const float* __restrict__ pred,
                        const float* __restrict__ tgt) {
    int id  = blockIdx.x * blockDim.x + threadIdx.x;      // 524288 threads
    int img = id >> 18;                                   // / (4*65536)
    int rem = id & ((1 << 18) - 1);
    int bat = rem >> 16;
    int n   = rem & (NPIX - 1);
    const float* src = (img ? tgt : pred) + bat * 3 * NPIX;
    float r = fminf(fmaxf(src[n           ], 0.f), 1.f);
    float g = fminf(fmaxf(src[n +    NPIX ], 0.f), 1.f);
    float b = fminf(fmaxf(src[n +  2*NPIX ], 0.f), 1.f);
    g_iy[id]   = sqrtf(fmaf(r, r, fmaf(g, g, fmaf(b, b, 1e-6f))));
    float lr = logf(r + 1e-6f);
    float lg = logf(g + 1e-6f);
    float lb = logf(b + 1e-6f);
    g_a   [id] = lr - lg;
    g_bdif[id] = lr - lb;
}

// -------------------------------------------------------------------- k2 ---
// 288 CTAs x 256 threads. CTA = (unit = bid%24, chunk = bid/24).
// Thread (ty,tx) owns an 8x8 tile of the 128x128 accumulator.
__global__ void __launch_bounds__(256, 2) k2_hist() {
    const int bid   = blockIdx.x;
    const int unit  = bid % NUNITS;
    const int chunk = bid / NUNITS;
    const int img   = unit / 12;
    const int bp    = unit % 12;
    const int bat   = bp / 3;
    const int pair  = bp % 3;
    const int off   = (img * NBATCH + bat) * NPIX;

    // Iu = cua*a + cub*b ; Iv = cva*a + cvb*b   (a=lR-lG, b=lR-lB)
    float cua, cub, cva, cvb;
    if      (pair == 0) { cua =  1.f; cub =  0.f; cva =  0.f; cvb =  1.f; }
    else if (pair == 1) { cua = -1.f; cub =  0.f; cva = -1.f; cvb =  1.f; }
    else                { cua =  0.f; cub = -1.f; cva =  1.f; cvb = -1.f; }

    const int t    = threadIdx.x;
    const int j    = t & 127;
    const int side = t >> 7;
    // bin centers pre-scaled by 1/sigma = 50
    const float musj = (-3.0f + (float)j * (6.0f / 127.0f)) * 50.0f;

    __shared__ float s_u[PIX], s_v[PIX], s_iy[PIX];
    __shared__ float s_du[PIX][HB];
    __shared__ float s_dv[PIX][HB];

    float acc[8][8];
#pragma unroll
    for (int i = 0; i < 8; i++)
#pragma unroll
        for (int k = 0; k < 8; k++) acc[i][k] = 0.f;

    const int r0 = (t >> 4) * 8;
    const int c0 = (t & 15) * 8;

    const int start = chunk * CHUNK_PX;
    const int end   = min(start + CHUNK_PX, NPIX);

    for (int base = start; base < end; base += PIX) {
        if (t < PIX) {
            float av = g_a   [off + base + t];
            float bv = g_bdif[off + base + t];
            s_u [t] = fmaf(cua, av, cub * bv) * 50.0f;
            s_v [t] = fmaf(cva, av, cvb * bv) * 50.0f;
            s_iy[t] = g_iy[off + base + t];
        }
        __syncthreads();

        if (side == 0) {
#pragma unroll
            for (int p = 0; p < PIX; p++) {
                float d = s_u[p] - musj;
                s_du[p][j] = s_iy[p] * __fdividef(1.0f, fmaf(d, d, 1.0f));
            }
        } else {
#pragma unroll
            for (int p = 0; p < PIX; p++) {
                float d = s_v[p] - musj;
                s_dv[p][j] = __fdividef(1.0f, fmaf(d, d, 1.0f));
            }
        }
        __syncthreads();

#pragma unroll
        for (int p = 0; p < PIX; p++) {
            float4 u0 = *(const float4*)&s_du[p][r0];
            float4 u1 = *(const float4*)&s_du[p][r0 + 4];
            float4 v0 = *(const float4*)&s_dv[p][c0];
            float4 v1 = *(const float4*)&s_dv[p][c0 + 4];
            float u[8] = {u0.x, u0.y, u0.z, u0.w, u1.x, u1.y, u1.z, u1.w};
            float v[8] = {v0.x, v0.y, v0.z, v0.w, v1.x, v1.y, v1.z, v1.w};
#pragma unroll
            for (int i = 0; i < 8; i++)
#pragma unroll
                for (int k = 0; k < 8; k++)
                    acc[i][k] = fmaf(u[i], v[k], acc[i][k]);
        }
        __syncthreads();
    }

    float* outp = g_partial + (unit * NCHUNK + chunk) * CELLS;
#pragma unroll
    for (int i = 0; i < 8; i++) {
        float4 w0 = make_float4(acc[i][0], acc[i][1], acc[i][2], acc[i][3]);
        float4 w1 = make_float4(acc[i][4], acc[i][5], acc[i][6], acc[i][7]);
        *(float4*)&outp[(r0 + i) * HB + c0    ] = w0;
        *(float4*)&outp[(r0 + i) * HB + c0 + 4] = w1;
    }
}

// -------------------------------------------------------------------- k3 ---
// 24*64 blocks x 256 threads: reduce chunk partials; per-block sums for norm.
__global__ void k3_reduce() {
    int blk  = blockIdx.x;
    int unit = blk >> 6;
    int seg  = blk & 63;
    int cell = seg * 256 + threadIdx.x;
    float s = 0.f;
#pragma unroll
    for (int c = 0; c < NCHUNK; c++)
        s += g_partial[(unit * NCHUNK + c) * CELLS + cell];
    g_hist[unit * CELLS + cell] = s;

    __shared__ float red[8];
#pragma unroll
    for (int o = 16; o > 0; o >>= 1) s += __shfl_down_sync(0xffffffffu, s, o);
    if ((threadIdx.x & 31) == 0) red[threadIdx.x >> 5] = s;
    __syncthreads();
    if (threadIdx.x == 0) {
        float tot = 0.f;
#pragma unroll
        for (int w = 0; w < 8; w++) tot += red[w];
        g_blocksum[blk] = tot;
    }
}

// ----------------------------------------------------------------- k4norm ---
__global__ void k4_norm() {
    int w = threadIdx.x >> 5, l = threadIdx.x & 31;   // 8 warps, warp w -> ib=w
    if (w < 8) {
        int img = w >> 2, bat = w & 3;
        int ub  = img * 12 + bat * 3;                 // 3 units -> 192 blocksums
        float s = 0.f;
        for (int i = l; i < 192; i += 32) s += g_blocksum[ub * 64 + i];
#pragma unroll
        for (int o = 16; o > 0; o >>= 1) s += __shfl_down_sync(0xffffffffu, s, o);
        if (l == 0) g_norm[w] = s + 1e-6f;
    }
}

// ----------------------------------------------------------------- k4loss ---
// 96 blocks x 256 threads over 4*3*16384 = 196608 (pred,target) cell pairs.
__global__ void k4_loss() {
    int blk = blockIdx.x;
    int t   = threadIdx.x;
    float s = 0.f;
#pragma unroll
    for (int q = 0; q < 8; q++) {
        int idx  = blk * 2048 + q * 256 + t;          // [0, 196608)
        int bp   = idx >> 14;                         // batch*3+pair
        int cell = idx & (CELLS - 1);
        int bat  = bp / 3;
        float p  = g_hist[ bp       * CELLS + cell];
        float tg = g_hist[(12 + bp) * CELLS + cell];
        float d  = sqrtf(tg / g_norm[4 + bat]) - sqrtf(p / g_norm[bat]);
        s += d * d;
    }
    __shared__ float red[8];
#pragma unroll
    for (int o = 16; o > 0; o >>= 1) s += __shfl_down_sync(0xffffffffu, s, o);
    if ((t & 31) == 0) red[t >> 5] = s;
    __syncthreads();
    if (t == 0) {
        float tot = 0.f;
#pragma unroll
        for (int w = 0; w < 8; w++) tot += red[w];
        g_losspart[blk] = tot;
    }
}

// ---------------------------------------------------------------- k4final ---
__global__ void k4_final(float* out) {
    int l = threadIdx.x;                              // 32 threads
    float s = 0.f;
    for (int i = l; i < 96; i += 32) s += g_losspart[i];
#pragma unroll
    for (int o = 16; o > 0; o >>= 1) s += __shfl_down_sync(0xffffffffu, s, o);
    if (l == 0)
        out[0] = sqrtf(s) * 0.70710678118654752f * 0.25f;  // (1/sqrt(2))/B
}

// ---------------------------------------------------------------------------
extern "C" void kernel_launch(void* const* d_in, const int* in_sizes, int n_in,
                              void* d_out, int out_size) {
    const float* pred = (const float*)d_in[0];
    const float* tgt  = (const float*)d_in[1];
    float* out = (float*)d_out;

    k1_prep <<<2048, 256>>>(pred, tgt);
    k2_hist <<<NUNITS * NCHUNK, 256>>>();
    k3_reduce<<<NUNITS * 64, 256>>>();
    k4_norm <<<1, 256>>>();
    k4_loss <<<96, 256>>>();
    k4_final<<<1, 32>>>(out);
}

// round 3
// speedup vs baseline: 1.2072x; 1.2072x over previous
#include <cuda_runtime.h>
#include <math.h>

// ---------------------------------------------------------------------------
// HistLoss: RGB-uv histogram Hellinger loss.  (Round 3: packed fma.rn.f32x2)
// B=4, C=3, H=W=256 -> N=65536 pixels. 128x128 bins, sigma=0.02, eps=1e-6.
// ---------------------------------------------------------------------------

#define NPIX    65536
#define HB      128
#define CELLS   (HB*HB)
#define NBATCH  4
#define NUNITS  24          // 2 images * 4 batch * 3 pairings
#define NCHUNK  12
#define CHUNK_PX 5472       // multiple of 16; 12*5472 >= 65536
#define PIX     16          // pixels per barrier period in k2

typedef unsigned long long u64t;

__device__ __forceinline__ u64t pack2(float lo, float hi) {
    u64t r; asm("mov.b64 %0, {%1, %2};" : "=l"(r) : "f"(lo), "f"(hi)); return r;
}
__device__ __forceinline__ void unpack2(u64t v, float& lo, float& hi) {
    asm("mov.b64 {%0, %1}, %2;" : "=f"(lo), "=f"(hi) : "l"(v));
}
__device__ __forceinline__ void ffma2(u64t& d, u64t a, u64t b) {
    asm("fma.rn.f32x2 %0, %1, %2, %0;" : "+l"(d) : "l"(a), "l"(b));
}

static __device__ float g_a      [2*NBATCH*NPIX];
static __device__ float g_bdif   [2*NBATCH*NPIX];
static __device__ float g_iy     [2*NBATCH*NPIX];
static __device__ float g_partial[NUNITS*NCHUNK*CELLS];   // ~18.9 MB
static __device__ float g_hist   [NUNITS*CELLS];
static __device__ float g_blocksum[NUNITS*64];
static __device__ float g_norm   [8];                     // [img*4+batch]
static __device__ float g_losspart[96];

// -------------------------------------------------------------------- k1 ---
__global__ void k1_prep(const float* __restrict__ pred,
                        const float* __restrict__ tgt) {
    int id  = blockIdx.x * blockDim.x + threadIdx.x;      // 524288 threads
    int img = id >> 18;
    int rem = id & ((1 << 18) - 1);
    int bat = rem >> 16;
    int n   = rem & (NPIX - 1);
    const float* src = (img ? tgt : pred) + bat * 3 * NPIX;
    float r = fminf(fmaxf(src[n          ], 0.f), 1.f);
    float g = fminf(fmaxf(src[n +   NPIX ], 0.f), 1.f);
    float b = fminf(fmaxf(src[n + 2*NPIX ], 0.f), 1.f);
    g_iy[id]   = sqrtf(fmaf(r, r, fmaf(g, g, fmaf(b, b, 1e-6f))));
    float lr = logf(r + 1e-6f);
    float lg = logf(g + 1e-6f);
    float lb = logf(b + 1e-6f);
    g_a   [id] = lr - lg;
    g_bdif[id] = lr - lb;
}

// -------------------------------------------------------------------- k2 ---
// 288 CTAs x 256 threads. CTA = (unit = bid%24, chunk = bid/24).
// Thread (ty,tx) owns an 8x8 tile of the 128x128 accumulator; accumulation
// runs on packed f32x2 FMAs (acc = 8 rows x 4 packed column-pairs).
__global__ void __launch_bounds__(256, 2) k2_hist() {
    const int bid   = blockIdx.x;
    const int unit  = bid % NUNITS;
    const int chunk = bid / NUNITS;
    const int img   = unit / 12;
    const int bp    = unit % 12;
    const int bat   = bp / 3;
    const int pair  = bp % 3;
    const int off   = (img * NBATCH + bat) * NPIX;

    // Iu = cua*a + cub*b ; Iv = cva*a + cvb*b   (a=lR-lG, b=lR-lB)
    float cua, cub, cva, cvb;
    if      (pair == 0) { cua =  1.f; cub =  0.f; cva =  0.f; cvb =  1.f; }
    else if (pair == 1) { cua = -1.f; cub =  0.f; cva = -1.f; cvb =  1.f; }
    else                { cua =  0.f; cub = -1.f; cva =  1.f; cvb = -1.f; }

    const int t    = threadIdx.x;
    const int j    = t & 127;
    const int side = t >> 7;
    // bin centers pre-scaled by 1/sigma = 50
    const float musj = (-3.0f + (float)j * (6.0f / 127.0f)) * 50.0f;

    __shared__ __align__(16) float s_u[PIX], s_v[PIX], s_iy[PIX];
    __shared__ __align__(16) float s_du[PIX][HB];
    __shared__ __align__(16) float s_dv[PIX][HB];

    u64t acc[8][4];
    const u64t z = pack2(0.f, 0.f);
#pragma unroll
    for (int i = 0; i < 8; i++)
#pragma unroll
        for (int k = 0; k < 4; k++) acc[i][k] = z;

    const int r0 = (t >> 4) * 8;
    const int c0 = (t & 15) * 8;

    const int start = chunk * CHUNK_PX;
    const int end   = min(start + CHUNK_PX, NPIX);

    for (int base = start; base < end; base += PIX) {
        if (t < PIX) {
            float av = g_a   [off + base + t];
            float bv = g_bdif[off + base + t];
            s_u [t] = fmaf(cua, av, cub * bv) * 50.0f;
            s_v [t] = fmaf(cva, av, cvb * bv) * 50.0f;
            s_iy[t] = g_iy[off + base + t];
        }
        __syncthreads();

        if (side == 0) {
#pragma unroll
            for (int p = 0; p < PIX; p++) {
                float d = s_u[p] - musj;
                s_du[p][j] = s_iy[p] * __fdividef(1.0f, fmaf(d, d, 1.0f));
            }
        } else {
#pragma unroll
            for (int p = 0; p < PIX; p++) {
                float d = s_v[p] - musj;
                s_dv[p][j] = __fdividef(1.0f, fmaf(d, d, 1.0f));
            }
        }
        __syncthreads();

#pragma unroll
        for (int p = 0; p < PIX; p++) {
            // v pairs: adjacent floats are already packed f32x2 values
            const u64t* vp = (const u64t*)&s_dv[p][c0];
            u64t v0 = vp[0], v1 = vp[1], v2 = vp[2], v3 = vp[3];
            float4 ua = *(const float4*)&s_du[p][r0];
            float4 ub = *(const float4*)&s_du[p][r0 + 4];
            float u[8] = {ua.x, ua.y, ua.z, ua.w, ub.x, ub.y, ub.z, ub.w};
#pragma unroll
            for (int i = 0; i < 8; i++) {
                u64t uu = pack2(u[i], u[i]);
                ffma2(acc[i][0], uu, v0);
                ffma2(acc[i][1], uu, v1);
                ffma2(acc[i][2], uu, v2);
                ffma2(acc[i][3], uu, v3);
            }
        }
        __syncthreads();
    }

    float* outp = g_partial + (unit * NCHUNK + chunk) * CELLS;
#pragma unroll
    for (int i = 0; i < 8; i++) {
        float w[8];
#pragma unroll
        for (int k = 0; k < 4; k++) unpack2(acc[i][k], w[2*k], w[2*k+1]);
        *(float4*)&outp[(r0 + i) * HB + c0    ] = make_float4(w[0], w[1], w[2], w[3]);
        *(float4*)&outp[(r0 + i) * HB + c0 + 4] = make_float4(w[4], w[5], w[6], w[7]);
    }
}

// -------------------------------------------------------------------- k3 ---
__global__ void k3_reduce() {
    int blk  = blockIdx.x;
    int unit = blk >> 6;
    int seg  = blk & 63;
    int cell = seg * 256 + threadIdx.x;
    float s = 0.f;
#pragma unroll
    for (int c = 0; c < NCHUNK; c++)
        s += g_partial[(unit * NCHUNK + c) * CELLS + cell];
    g_hist[unit * CELLS + cell] = s;

    __shared__ float red[8];
#pragma unroll
    for (int o = 16; o > 0; o >>= 1) s += __shfl_down_sync(0xffffffffu, s, o);
    if ((threadIdx.x & 31) == 0) red[threadIdx.x >> 5] = s;
    __syncthreads();
    if (threadIdx.x == 0) {
        float tot = 0.f;
#pragma unroll
        for (int w = 0; w < 8; w++) tot += red[w];
        g_blocksum[blk] = tot;
    }
}

// ----------------------------------------------------------------- k4norm ---
__global__ void k4_norm() {
    int w = threadIdx.x >> 5, l = threadIdx.x & 31;
    if (w < 8) {
        int img = w >> 2, bat = w & 3;
        int ub  = img * 12 + bat * 3;
        float s = 0.f;
        for (int i = l; i < 192; i += 32) s += g_blocksum[ub * 64 + i];
#pragma unroll
        for (int o = 16; o > 0; o >>= 1) s += __shfl_down_sync(0xffffffffu, s, o);
        if (l == 0) g_norm[w] = s + 1e-6f;
    }
}

// ----------------------------------------------------------------- k4loss ---
__global__ void k4_loss() {
    int blk = blockIdx.x;
    int t   = threadIdx.x;
    float s = 0.f;
#pragma unroll
    for (int q = 0; q < 8; q++) {
        int idx  = blk * 2048 + q * 256 + t;          // [0, 196608)
        int bp   = idx >> 14;
        int cell = idx & (CELLS - 1);
        int bat  = bp / 3;
        float p  = g_hist[ bp       * CELLS + cell];
        float tg = g_hist[(12 + bp) * CELLS + cell];
        float d  = sqrtf(tg / g_norm[4 + bat]) - sqrtf(p / g_norm[bat]);
        s += d * d;
    }
    __shared__ float red[8];
#pragma unroll
    for (int o = 16; o > 0; o >>= 1) s += __shfl_down_sync(0xffffffffu, s, o);
    if ((t & 31) == 0) red[t >> 5] = s;
    __syncthreads();
    if (t == 0) {
        float tot = 0.f;
#pragma unroll
        for (int w = 0; w < 8; w++) tot += red[w];
        g_losspart[blk] = tot;
    }
}

// ---------------------------------------------------------------- k4final ---
__global__ void k4_final(float* out) {
    int l = threadIdx.x;                              // 32 threads
    float s = 0.f;
    for (int i = l; i < 96; i += 32) s += g_losspart[i];
#pragma unroll
    for (int o = 16; o > 0; o >>= 1) s += __shfl_down_sync(0xffffffffu, s, o);
    if (l == 0)
        out[0] = sqrtf(s) * 0.70710678118654752f * 0.25f;  // (1/sqrt(2))/B
}

// ---------------------------------------------------------------------------
extern "C" void kernel_launch(void* const* d_in, const int* in_sizes, int n_in,
                              void* d_out, int out_size) {
    const float* pred = (const float*)d_in[0];
    const float* tgt  = (const float*)d_in[1];
    float* out = (float*)d_out;

    k1_prep <<<2048, 256>>>(pred, tgt);
    k2_hist <<<NUNITS * NCHUNK, 256>>>();
    k3_reduce<<<NUNITS * 64, 256>>>();
    k4_norm <<<1, 256>>>();
    k4_loss <<<96, 256>>>();
    k4_final<<<1, 32>>>(out);
}

// round 5
// speedup vs baseline: 4.1080x; 3.4030x over previous
#include <cuda_runtime.h>
#include <cuda_bf16.h>
#include <math.h>
#include <stdint.h>

// ---------------------------------------------------------------------------
// HistLoss: RGB-uv histogram Hellinger loss. (Round 5: mma.sync bf16 HMMA)
// hist = A @ B^T per (img,batch,pair):  A[128,K]=Iy*k_u, B[128,K]=k_v,
// operands generated on the fly as bf16 in smem, accumulated fp32 in
// per-warp register fragments via mma.sync.m16n8k16 (baseline PTX, no tcgen05).
// ---------------------------------------------------------------------------

#define NPIX    65536
#define HB      128
#define CELLS   (HB*HB)
#define NBATCH  4
#define NUNITS  24          // 2 images * 4 batch * 3 pairings
#define NCHUNK  12
#define CHUNK_PX 5504       // 86*64; chunk 11 gets 4992 = 78*64 (all full tiles)
#define KT      64          // pixels per staged tile
#define PITCH   72          // halves per smem row (144 B; +16B phase per row)

static __device__ float g_a      [2*NBATCH*NPIX];
static __device__ float g_bdif   [2*NBATCH*NPIX];
static __device__ float g_iy     [2*NBATCH*NPIX];
static __device__ float g_partial[NUNITS*NCHUNK*CELLS];   // ~18.9 MB
static __device__ float g_hist   [NUNITS*CELLS];
static __device__ float g_blocksum[NUNITS*64];
static __device__ float g_norm   [8];
static __device__ float g_losspart[96];

__device__ __forceinline__ uint32_t smem_u32(const void* p) {
    uint32_t a;
    asm("{ .reg .u64 t; cvta.to.shared.u64 t, %1; cvt.u32.u64 %0, t; }"
        : "=r"(a) : "l"(p));
    return a;
}
__device__ __forceinline__ void ldm_x4(uint32_t& r0, uint32_t& r1,
                                       uint32_t& r2, uint32_t& r3, uint32_t a) {
    asm volatile("ldmatrix.sync.aligned.m8n8.x4.shared.b16 {%0,%1,%2,%3}, [%4];"
                 : "=r"(r0), "=r"(r1), "=r"(r2), "=r"(r3) : "r"(a));
}
__device__ __forceinline__ void mma16816(float* d, uint32_t a0, uint32_t a1,
                                         uint32_t a2, uint32_t a3,
                                         uint32_t b0, uint32_t b1) {
    asm volatile(
        "mma.sync.aligned.m16n8k16.row.col.f32.bf16.bf16.f32 "
        "{%0,%1,%2,%3}, {%4,%5,%6,%7}, {%8,%9}, {%0,%1,%2,%3};"
        : "+f"(d[0]), "+f"(d[1]), "+f"(d[2]), "+f"(d[3])
        : "r"(a0), "r"(a1), "r"(a2), "r"(a3), "r"(b0), "r"(b1));
}

// -------------------------------------------------------------------- k1 ---
__global__ void k1_prep(const float* __restrict__ pred,
                        const float* __restrict__ tgt) {
    int id  = blockIdx.x * blockDim.x + threadIdx.x;      // 524288 threads
    int img = id >> 18;
    int rem = id & ((1 << 18) - 1);
    int bat = rem >> 16;
    int n   = rem & (NPIX - 1);
    const float* src = (img ? tgt : pred) + bat * 3 * NPIX;
    float r = fminf(fmaxf(src[n          ], 0.f), 1.f);
    float g = fminf(fmaxf(src[n +   NPIX ], 0.f), 1.f);
    float b = fminf(fmaxf(src[n + 2*NPIX ], 0.f), 1.f);
    g_iy[id]   = sqrtf(fmaf(r, r, fmaf(g, g, fmaf(b, b, 1e-6f))));
    float lr = logf(r + 1e-6f);
    float lg = logf(g + 1e-6f);
    float lb = logf(b + 1e-6f);
    g_a   [id] = lr - lg;
    g_bdif[id] = lr - lb;
}

// -------------------------------------------------------------------- k2 ---
// 288 CTAs x 256 threads. CTA = (unit = bid%24, chunk = bid/24).
// Per 64-px tile: eval phase writes bf16 A/B tiles [bin][px] (pitch 72
// halves), mma phase: warp w accumulates rows 16w..16w+15 x 128 cols.
__global__ void __launch_bounds__(256, 2) k2_hist() {
    const int bid   = blockIdx.x;
    const int unit  = bid % NUNITS;
    const int chunk = bid / NUNITS;
    const int img   = unit / 12;
    const int bp    = unit % 12;
    const int bat   = bp / 3;
    const int pair  = bp % 3;
    const int off   = (img * NBATCH + bat) * NPIX;

    // Iu = cua*a + cub*b ; Iv = cva*a + cvb*b   (a=lR-lG, b=lR-lB)
    float cua, cub, cva, cvb;
    if      (pair == 0) { cua =  1.f; cub =  0.f; cva =  0.f; cvb =  1.f; }
    else if (pair == 1) { cua = -1.f; cub =  0.f; cva = -1.f; cvb =  1.f; }
    else                { cua =  0.f; cub = -1.f; cva =  1.f; cvb = -1.f; }

    const int t    = threadIdx.x;
    const int wid  = t >> 5;
    const int lane = t & 31;

    __shared__ __align__(16) __nv_bfloat16 sA[HB * PITCH];   // 18 KB
    __shared__ __align__(16) __nv_bfloat16 sB[HB * PITCH];   // 18 KB
    __shared__ float s_u[KT], s_v[KT], s_iy[KT];

    float acc[16][4];
#pragma unroll
    for (int j = 0; j < 16; j++)
#pragma unroll
        for (int q = 0; q < 4; q++) acc[j][q] = 0.f;

    // eval-role: thread = one bin-row of A (t<128) or B (t>=128)
    const int   r    = t & 127;
    const bool  isA  = t < 128;
    const float mus  = (-3.0f + (float)r * (6.0f / 127.0f)) * 50.0f;
    char* tile = (char*)(isA ? sA : sB);
    const float* xs  = isA ? s_u : s_v;
    const int   prot = ((r >> 3) & 3) * 8;    // STS bank-conflict rotation

    // mma-role addressing (halves->bytes: *2)
    const uint32_t aAddr = smem_u32(sA) + (16*wid + (lane & 15))*2*PITCH
                                        + (lane >> 4)*16;
    const uint32_t bBase = smem_u32(sB) + (lane & 15)*2*PITCH + (lane >> 4)*16;

    const int start  = chunk * CHUNK_PX;
    const int end    = min(start + CHUNK_PX, NPIX);
    const int ntiles = (end - start) / KT;     // 86 or 78, exact

    for (int tl = 0; tl < ntiles; ++tl) {
        const int base = start + tl * KT;
        if (t < KT) {
            float av = g_a   [off + base + t];
            float bv = g_bdif[off + base + t];
            s_u [t] = fmaf(cua, av, cub * bv) * 50.0f;
            s_v [t] = fmaf(cva, av, cvb * bv) * 50.0f;
            s_iy[t] = g_iy[off + base + t];
        }
        __syncthreads();   // px visible; prev-iter mma done (sA/sB reusable)

#pragma unroll 8
        for (int pp = 0; pp < KT / 2; ++pp) {
            const int p2 = (pp + prot) & (KT / 2 - 1);
            float x0 = xs[2 * p2], x1 = xs[2 * p2 + 1];
            float d0 = x0 - mus,   d1 = x1 - mus;
            float q0 = fmaf(d0, d0, 1.0f);
            float q1 = fmaf(d1, d1, 1.0f);
            float k0, k1;
            asm("rcp.approx.ftz.f32 %0, %1;" : "=f"(k0) : "f"(q0));
            asm("rcp.approx.ftz.f32 %0, %1;" : "=f"(k1) : "f"(q1));
            if (isA) { k0 *= s_iy[2 * p2]; k1 *= s_iy[2 * p2 + 1]; }
            uint32_t pk;   // lo half = even px, hi half = odd px
            asm("cvt.rn.satfinite.bf16x2.f32 %0, %1, %2;" : "=r"(pk) : "f"(k1), "f"(k0));
            *(uint32_t*)(tile + r * (2 * PITCH) + p2 * 4) = pk;
        }
        __syncthreads();   // tiles complete -> mma

#pragma unroll
        for (int kk = 0; kk < 4; ++kk) {       // 4 x K=16 slices
            uint32_t a0, a1, a2, a3;
            ldm_x4(a0, a1, a2, a3, aAddr + kk * 32);
            uint32_t bA = bBase + kk * 32;
#pragma unroll
            for (int j2 = 0; j2 < 8; ++j2) {   // n16 blocks
                uint32_t b0, b1, b2, b3;
                ldm_x4(b0, b1, b2, b3, bA + j2 * 16 * 2 * PITCH);
                mma16816(acc[2*j2    ], a0, a1, a2, a3, b0, b2);
                mma16816(acc[2*j2 + 1], a0, a1, a2, a3, b1, b3);
            }
        }
    }

    // Epilogue: fragment-indexed stores.
    // thread: rows 16*wid + lane/4 (+8), cols 16*j2 + 8*h + 2*(lane%4)
    float* outp = g_partial + (unit * NCHUNK + chunk) * CELLS;
    const int row0 = 16 * wid + (lane >> 2);
    const int cofs = 2 * (lane & 3);
#pragma unroll
    for (int j2 = 0; j2 < 8; ++j2)
#pragma unroll
        for (int h = 0; h < 2; ++h) {
            const int c = 16 * j2 + 8 * h + cofs;
            float* a4 = acc[2 * j2 + h];
            *(float2*)(outp +  row0      * HB + c) = make_float2(a4[0], a4[1]);
            *(float2*)(outp + (row0 + 8) * HB + c) = make_float2(a4[2], a4[3]);
        }
}

// -------------------------------------------------------------------- k3 ---
__global__ void k3_reduce() {
    int blk  = blockIdx.x;
    int unit = blk >> 6;
    int seg  = blk & 63;
    int cell = seg * 256 + threadIdx.x;
    float s = 0.f;
#pragma unroll
    for (int c = 0; c < NCHUNK; c++)
        s += g_partial[(unit * NCHUNK + c) * CELLS + cell];
    g_hist[unit * CELLS + cell] = s;

    __shared__ float red[8];
#pragma unroll
    for (int o = 16; o > 0; o >>= 1) s += __shfl_down_sync(0xffffffffu, s, o);
    if ((threadIdx.x & 31) == 0) red[threadIdx.x >> 5] = s;
    __syncthreads();
    if (threadIdx.x == 0) {
        float tot = 0.f;
#pragma unroll
        for (int w = 0; w < 8; w++) tot += red[w];
        g_blocksum[blk] = tot;
    }
}

// ----------------------------------------------------------------- k4norm ---
__global__ void k4_norm() {
    int w = threadIdx.x >> 5, l = threadIdx.x & 31;
    if (w < 8) {
        int img = w >> 2, bat = w & 3;
        int ub  = img * 12 + bat * 3;
        float s = 0.f;
        for (int i = l; i < 192; i += 32) s += g_blocksum[ub * 64 + i];
#pragma unroll
        for (int o = 16; o > 0; o >>= 1) s += __shfl_down_sync(0xffffffffu, s, o);
        if (l == 0) g_norm[w] = s + 1e-6f;
    }
}

// ----------------------------------------------------------------- k4loss ---
__global__ void k4_loss() {
    int blk = blockIdx.x;
    int t   = threadIdx.x;
    float s = 0.f;
#pragma unroll
    for (int q = 0; q < 8; q++) {
        int idx  = blk * 2048 + q * 256 + t;              // [0, 196608)
        int bp   = idx >> 14;
        int cell = idx & (CELLS - 1);
        int bat  = bp / 3;
        float p  = g_hist[ bp       * CELLS + cell];
        float tg = g_hist[(12 + bp) * CELLS + cell];
        float d  = sqrtf(tg / g_norm[4 + bat]) - sqrtf(p / g_norm[bat]);
        s += d * d;
    }
    __shared__ float red[8];
#pragma unroll
    for (int o = 16; o > 0; o >>= 1) s += __shfl_down_sync(0xffffffffu, s, o);
    if ((t & 31) == 0) red[t >> 5] = s;
    __syncthreads();
    if (t == 0) {
        float tot = 0.f;
#pragma unroll
        for (int w = 0; w < 8; w++) tot += red[w];
        g_losspart[blk] = tot;
    }
}

// ---------------------------------------------------------------- k4final ---
__global__ void k4_final(float* out) {
    int l = threadIdx.x;
    float s = 0.f;
    for (int i = l; i < 96; i += 32) s += g_losspart[i];
#pragma unroll
    for (int o = 16; o > 0; o >>= 1) s += __shfl_down_sync(0xffffffffu, s, o);
    if (l == 0)
        out[0] = sqrtf(s) * 0.70710678118654752f * 0.25f;  // (1/sqrt(2))/B
}

// ---------------------------------------------------------------------------
extern "C" void kernel_launch(void* const* d_in, const int* in_sizes, int n_in,
                              void* d_out, int out_size) {
    const float* pred = (const float*)d_in[0];
    const float* tgt  = (const float*)d_in[1];
    float* out = (float*)d_out;

    k1_prep <<<2048, 256>>>(pred, tgt);
    k2_hist <<<NUNITS * NCHUNK, 256>>>();
    k3_reduce<<<NUNITS * 64, 256>>>();
    k4_norm <<<1, 256>>>();
    k4_loss <<<96, 256>>>();
    k4_final<<<1, 32>>>(out);
}

// round 6
// speedup vs baseline: 4.7165x; 1.1481x over previous
#include <cuda_runtime.h>
#include <cuda_bf16.h>
#include <math.h>
#include <stdint.h>

// ---------------------------------------------------------------------------
// HistLoss: RGB-uv histogram Hellinger loss. (Round 6: HMMA + double-buffer,
// conflict-free STS, shared-RCP eval, fused tail reduction)
// ---------------------------------------------------------------------------

#define NPIX    65536
#define HB      128
#define CELLS   (HB*HB)
#define NBATCH  4
#define NUNITS  24
#define NCHUNK  12
#define CHUNK_PX 5504       // 86*64; chunk 11 gets 4992 = 78*64 (all full tiles)
#define KT      64          // pixels per staged tile
#define PITCH   72          // halves per smem row (144 B)
#define TILE_BYTES (HB*PITCH*2)       // 18432 (one operand tile)
#define BUF_BYTES  (2*TILE_BYTES)     // 36864 (A+B)
#define STAGE_OFF  (2*BUF_BYTES)      // 73728
#define SMEM_TOTAL (STAGE_OFF + 4*192*4)   // 76800

static __device__ float g_a      [2*NBATCH*NPIX];
static __device__ float g_bdif   [2*NBATCH*NPIX];
static __device__ float g_iy     [2*NBATCH*NPIX];
static __device__ float g_partial[NUNITS*NCHUNK*CELLS];   // ~18.9 MB
static __device__ float g_bsp[12*64];
static __device__ float g_bst[12*64];
static __device__ float g_bss[12*64];

__device__ __forceinline__ uint32_t smem_u32(const void* p) {
    uint32_t a;
    asm("{ .reg .u64 t; cvta.to.shared.u64 t, %1; cvt.u32.u64 %0, t; }"
        : "=r"(a) : "l"(p));
    return a;
}
__device__ __forceinline__ void ldm_x4(uint32_t& r0, uint32_t& r1,
                                       uint32_t& r2, uint32_t& r3, uint32_t a) {
    asm volatile("ldmatrix.sync.aligned.m8n8.x4.shared.b16 {%0,%1,%2,%3}, [%4];"
                 : "=r"(r0), "=r"(r1), "=r"(r2), "=r"(r3) : "r"(a));
}
__device__ __forceinline__ void mma16816(float* d, uint32_t a0, uint32_t a1,
                                         uint32_t a2, uint32_t a3,
                                         uint32_t b0, uint32_t b1) {
    asm volatile(
        "mma.sync.aligned.m16n8k16.row.col.f32.bf16.bf16.f32 "
        "{%0,%1,%2,%3}, {%4,%5,%6,%7}, {%8,%9}, {%0,%1,%2,%3};"
        : "+f"(d[0]), "+f"(d[1]), "+f"(d[2]), "+f"(d[3])
        : "r"(a0), "r"(a1), "r"(a2), "r"(a3), "r"(b0), "r"(b1));
}

// -------------------------------------------------------------------- k1 ---
__global__ void k1_prep(const float* __restrict__ pred,
                        const float* __restrict__ tgt) {
    int id  = blockIdx.x * blockDim.x + threadIdx.x;      // 524288 threads
    int img = id >> 18;
    int rem = id & ((1 << 18) - 1);
    int bat = rem >> 16;
    int n   = rem & (NPIX - 1);
    const float* src = (img ? tgt : pred) + bat * 3 * NPIX;
    float r = fminf(fmaxf(src[n          ], 0.f), 1.f);
    float g = fminf(fmaxf(src[n +   NPIX ], 0.f), 1.f);
    float b = fminf(fmaxf(src[n + 2*NPIX ], 0.f), 1.f);
    g_iy[id]   = sqrtf(fmaf(r, r, fmaf(g, g, fmaf(b, b, 1e-6f))));
    float lr = logf(r + 1e-6f);
    float lg = logf(g + 1e-6f);
    float lb = logf(b + 1e-6f);
    g_a   [id] = lr - lg;
    g_bdif[id] = lr - lb;
}

// -------------------------------------------------------------------- k2 ---
// 288 CTAs x 256 threads. CTA = (unit = bid%24, chunk = bid/24).
// Double-buffered 64-px tiles; per iteration: eval(tl) into buf[tl&1] while
// mma(tl-1) reads buf[(tl-1)&1]; 4-slot pixel staging prefetched 2 ahead;
// single __syncthreads per tile.
__global__ void __launch_bounds__(256, 2) k2_hist() {
    extern __shared__ char dyn[];
    const int bid   = blockIdx.x;
    const int unit  = bid % NUNITS;
    const int chunk = bid / NUNITS;
    const int img   = unit / 12;
    const int bp    = unit % 12;
    const int bat   = bp / 3;
    const int pair  = bp % 3;
    const int off   = (img * NBATCH + bat) * NPIX;

    float cua, cub, cva, cvb;
    if      (pair == 0) { cua =  1.f; cub =  0.f; cva =  0.f; cvb =  1.f; }
    else if (pair == 1) { cua = -1.f; cub =  0.f; cva = -1.f; cvb =  1.f; }
    else                { cua =  0.f; cub = -1.f; cva =  1.f; cvb = -1.f; }

    const int t    = threadIdx.x;
    const int wid  = t >> 5;
    const int lane = t & 31;

    float* stage = (float*)(dyn + STAGE_OFF);   // [4][3][64] : u, v, iy

    float acc[16][4];
#pragma unroll
    for (int j = 0; j < 16; j++)
#pragma unroll
        for (int q = 0; q < 4; q++) acc[j][q] = 0.f;

    // eval role
    const int   r    = t & 127;
    const bool  isA  = t < 128;
    const float mus  = (-3.0f + (float)r * (6.0f / 127.0f)) * 50.0f;
    const int   prot = (r >> 3) & 3;            // conflict-free word rotation
    char* rowp = dyn + (isA ? 0 : TILE_BYTES) + r * (2 * PITCH);

    // mma role addressing
    const uint32_t sbase = smem_u32(dyn);
    const uint32_t aAddr = sbase + (16*wid + (lane & 15))*2*PITCH + (lane >> 4)*16;
    const uint32_t bAddr = sbase + TILE_BYTES + (lane & 15)*2*PITCH + (lane >> 4)*16;

    const int start  = chunk * CHUNK_PX;
    const int end    = min(start + CHUNK_PX, NPIX);
    const int ntiles = (end - start) / KT;       // 86 or 78, exact

    // prologue: stage px(0), px(1)
    if (t < 128) {
        const int tl0 = t >> 6, i = t & 63;
        float* st = stage + (tl0 & 3) * 192;
        const int gi = off + start + tl0 * KT + i;
        float av = g_a[gi], bv = g_bdif[gi];
        st[i]       = fmaf(cua, av, cub * bv) * 50.0f;
        st[64 + i]  = fmaf(cva, av, cvb * bv) * 50.0f;
        st[128 + i] = g_iy[gi];
    }
    __syncthreads();

    for (int tl = 0; tl < ntiles; ++tl) {
        // ---- eval(tl) into buf[tl&1] ----
        {
            const float* st = stage + (tl & 3) * 192;
            const float* xs = st + (isA ? 0 : 64);
            const float* iy = st + 128;
            char* tile = rowp + (tl & 1) * BUF_BYTES;
#pragma unroll 8
            for (int pp = 0; pp < 32; ++pp) {
                const int p2 = (pp + prot) & 31;
                float x0 = xs[2 * p2], x1 = xs[2 * p2 + 1];
                float d0 = x0 - mus,   d1 = x1 - mus;
                float q0 = fmaf(d0, d0, 1.0f);
                float q1 = fmaf(d1, d1, 1.0f);
                float qq = q0 * q1, rr;
                asm("rcp.approx.ftz.f32 %0, %1;" : "=f"(rr) : "f"(qq));
                float k0 = rr * q1, k1 = rr * q0;
                if (isA) { k0 *= iy[2 * p2]; k1 *= iy[2 * p2 + 1]; }
                uint32_t pk;   // lo = even px, hi = odd px
                asm("cvt.rn.satfinite.bf16x2.f32 %0, %1, %2;" : "=r"(pk) : "f"(k1), "f"(k0));
                *(uint32_t*)(tile + p2 * 4) = pk;
            }
        }

        // ---- mma(tl-1) on buf[(tl-1)&1] (independent of eval above) ----
        if (tl > 0) {
            const uint32_t bo = ((tl - 1) & 1) * BUF_BYTES;
#pragma unroll
            for (int kk = 0; kk < 4; ++kk) {
                uint32_t a0, a1, a2, a3;
                ldm_x4(a0, a1, a2, a3, aAddr + bo + kk * 32);
                const uint32_t bA = bAddr + bo + kk * 32;
#pragma unroll
                for (int j2 = 0; j2 < 8; ++j2) {
                    uint32_t b0, b1, b2, b3;
                    ldm_x4(b0, b1, b2, b3, bA + j2 * 16 * 2 * PITCH);
                    mma16816(acc[2*j2    ], a0, a1, a2, a3, b0, b2);
                    mma16816(acc[2*j2 + 1], a0, a1, a2, a3, b1, b3);
                }
            }
        }

        // ---- prefetch px(tl+2) ----
        if (t < 64 && tl + 2 < ntiles) {
            float* st = stage + ((tl + 2) & 3) * 192;
            const int gi = off + start + (tl + 2) * KT + t;
            float av = g_a[gi], bv = g_bdif[gi];
            st[t]       = fmaf(cua, av, cub * bv) * 50.0f;
            st[64 + t]  = fmaf(cva, av, cvb * bv) * 50.0f;
            st[128 + t] = g_iy[gi];
        }
        __syncthreads();
    }

    // ---- final mma(ntiles-1) ----
    {
        const uint32_t bo = ((ntiles - 1) & 1) * BUF_BYTES;
#pragma unroll
        for (int kk = 0; kk < 4; ++kk) {
            uint32_t a0, a1, a2, a3;
            ldm_x4(a0, a1, a2, a3, aAddr + bo + kk * 32);
            const uint32_t bA = bAddr + bo + kk * 32;
#pragma unroll
            for (int j2 = 0; j2 < 8; ++j2) {
                uint32_t b0, b1, b2, b3;
                ldm_x4(b0, b1, b2, b3, bA + j2 * 16 * 2 * PITCH);
                mma16816(acc[2*j2    ], a0, a1, a2, a3, b0, b2);
                mma16816(acc[2*j2 + 1], a0, a1, a2, a3, b1, b3);
            }
        }
    }

    // Epilogue: fragment-indexed stores.
    float* outp = g_partial + (unit * NCHUNK + chunk) * CELLS;
    const int row0 = 16 * wid + (lane >> 2);
    const int cofs = 2 * (lane & 3);
#pragma unroll
    for (int j2 = 0; j2 < 8; ++j2)
#pragma unroll
        for (int h = 0; h < 2; ++h) {
            const int c = 16 * j2 + 8 * h + cofs;
            float* a4 = acc[2 * j2 + h];
            *(float2*)(outp +  row0      * HB + c) = make_float2(a4[0], a4[1]);
            *(float2*)(outp + (row0 + 8) * HB + c) = make_float2(a4[2], a4[3]);
        }
}

// -------------------------------------------------------------------- k3 ---
// 768 blocks: bp = blk>>6 (batch*3+pair), seg = blk&63. Sums 12 chunk
// partials for pred (unit bp) and target (unit 12+bp); accumulates
// block sums of p, t, sqrt(p*t) for the fused Hellinger tail.
__global__ void k3_reduce() {
    int blk  = blockIdx.x;
    int bp   = blk >> 6;
    int seg  = blk & 63;
    int cell = seg * 256 + threadIdx.x;
    float p = 0.f, tt = 0.f;
#pragma unroll
    for (int c = 0; c < NCHUNK; c++) {
        p  += g_partial[((bp     ) * NCHUNK + c) * CELLS + cell];
        tt += g_partial[((12 + bp) * NCHUNK + c) * CELLS + cell];
    }
    float s = sqrtf(p * tt);

    __shared__ float redp[8], redt[8], reds[8];
#pragma unroll
    for (int o = 16; o > 0; o >>= 1) {
        p  += __shfl_down_sync(0xffffffffu, p,  o);
        tt += __shfl_down_sync(0xffffffffu, tt, o);
        s  += __shfl_down_sync(0xffffffffu, s,  o);
    }
    if ((threadIdx.x & 31) == 0) {
        redp[threadIdx.x >> 5] = p;
        redt[threadIdx.x >> 5] = tt;
        reds[threadIdx.x >> 5] = s;
    }
    __syncthreads();
    if (threadIdx.x == 0) {
        float sp = 0.f, st = 0.f, ss = 0.f;
#pragma unroll
        for (int w = 0; w < 8; w++) { sp += redp[w]; st += redt[w]; ss += reds[w]; }
        g_bsp[blk] = sp; g_bst[blk] = st; g_bss[blk] = ss;
    }
}

// ---------------------------------------------------------------- k4final ---
// loss^2*2*B^2 = sum_bat [ sp/Np + st/Nt - 2*ss/sqrt(Np*Nt) ]
__global__ void k4_final(float* out) {
    int w = threadIdx.x >> 5, lane = threadIdx.x & 31;
    __shared__ float sl[4];
    if (w < 4) {
        float sp = 0.f, st = 0.f, ss = 0.f;
        for (int i = lane; i < 192; i += 32) {
            int blk = (3 * w) * 64 + i;        // 192 contiguous blocks per bat
            sp += g_bsp[blk]; st += g_bst[blk]; ss += g_bss[blk];
        }
#pragma unroll
        for (int o = 16; o > 0; o >>= 1) {
            sp += __shfl_down_sync(0xffffffffu, sp, o);
            st += __shfl_down_sync(0xffffffffu, st, o);
            ss += __shfl_down_sync(0xffffffffu, ss, o);
        }
        if (lane == 0) {
            float Np = sp + 1e-6f, Nt = st + 1e-6f;
            sl[w] = sp / Np + st / Nt - 2.f * ss / sqrtf(Np * Nt);
        }
    }
    __syncthreads();
    if (threadIdx.x == 0) {
        float tot = fmaxf(sl[0] + sl[1] + sl[2] + sl[3], 0.f);
        out[0] = sqrtf(tot) * 0.70710678118654752f * 0.25f;  // (1/sqrt2)/B
    }
}

// ---------------------------------------------------------------------------
extern "C" void kernel_launch(void* const* d_in, const int* in_sizes, int n_in,
                              void* d_out, int out_size) {
    const float* pred = (const float*)d_in[0];
    const float* tgt  = (const float*)d_in[1];
    float* out = (float*)d_out;

    cudaFuncSetAttribute(k2_hist, cudaFuncAttributeMaxDynamicSharedMemorySize,
                         SMEM_TOTAL);

    k1_prep <<<2048, 256>>>(pred, tgt);
    k2_hist <<<NUNITS * NCHUNK, 256, SMEM_TOTAL>>>();
    k3_reduce<<<12 * 64, 256>>>();
    k4_final<<<1, 128>>>(out);
}

// round 7
// speedup vs baseline: 4.9074x; 1.0405x over previous
#include <cuda_runtime.h>
#include <cuda_bf16.h>
#include <math.h>
#include <stdint.h>

// ---------------------------------------------------------------------------
// HistLoss: RGB-uv histogram Hellinger loss. (Round 7: 4x2 warp retile +
// packed f32x2 eval; double-buffered HMMA pipeline; fused tail)
// ---------------------------------------------------------------------------

#define NPIX    65536
#define HB      128
#define CELLS   (HB*HB)
#define NBATCH  4
#define NUNITS  24
#define NCHUNK  12
#define CHUNK_PX 5504       // 86*64; chunk 11 gets 4992 = 78*64 (all full tiles)
#define KT      64          // pixels per staged tile
#define PITCH   72          // halves per smem row (144 B)
#define TILE_BYTES (HB*PITCH*2)       // 18432 (one operand tile)
#define BUF_BYTES  (2*TILE_BYTES)     // 36864 (A+B)
#define STAGE_OFF  (2*BUF_BYTES)      // 73728
#define SMEM_TOTAL (STAGE_OFF + 4*192*4)   // 76800

typedef unsigned long long u64t;

static __device__ float g_a      [2*NBATCH*NPIX];
static __device__ float g_bdif   [2*NBATCH*NPIX];
static __device__ float g_iy     [2*NBATCH*NPIX];
static __device__ float g_partial[NUNITS*NCHUNK*CELLS];   // ~18.9 MB
static __device__ float g_bsp[12*64];
static __device__ float g_bst[12*64];
static __device__ float g_bss[12*64];

__device__ __forceinline__ uint32_t smem_u32(const void* p) {
    uint32_t a;
    asm("{ .reg .u64 t; cvta.to.shared.u64 t, %1; cvt.u32.u64 %0, t; }"
        : "=r"(a) : "l"(p));
    return a;
}
__device__ __forceinline__ u64t pack2(float lo, float hi) {
    u64t r; asm("mov.b64 %0, {%1, %2};" : "=l"(r) : "f"(lo), "f"(hi)); return r;
}
__device__ __forceinline__ void ldm_x4(uint32_t& r0, uint32_t& r1,
                                       uint32_t& r2, uint32_t& r3, uint32_t a) {
    asm volatile("ldmatrix.sync.aligned.m8n8.x4.shared.b16 {%0,%1,%2,%3}, [%4];"
                 : "=r"(r0), "=r"(r1), "=r"(r2), "=r"(r3) : "r"(a));
}
__device__ __forceinline__ void mma16816(float* d, uint32_t a0, uint32_t a1,
                                         uint32_t a2, uint32_t a3,
                                         uint32_t b0, uint32_t b1) {
    asm volatile(
        "mma.sync.aligned.m16n8k16.row.col.f32.bf16.bf16.f32 "
        "{%0,%1,%2,%3}, {%4,%5,%6,%7}, {%8,%9}, {%0,%1,%2,%3};"
        : "+f"(d[0]), "+f"(d[1]), "+f"(d[2]), "+f"(d[3])
        : "r"(a0), "r"(a1), "r"(a2), "r"(a3), "r"(b0), "r"(b1));
}

// -------------------------------------------------------------------- k1 ---
__global__ void k1_prep(const float* __restrict__ pred,
                        const float* __restrict__ tgt) {
    int id  = blockIdx.x * blockDim.x + threadIdx.x;      // 524288 threads
    int img = id >> 18;
    int rem = id & ((1 << 18) - 1);
    int bat = rem >> 16;
    int n   = rem & (NPIX - 1);
    const float* src = (img ? tgt : pred) + bat * 3 * NPIX;
    float r = fminf(fmaxf(src[n          ], 0.f), 1.f);
    float g = fminf(fmaxf(src[n +   NPIX ], 0.f), 1.f);
    float b = fminf(fmaxf(src[n + 2*NPIX ], 0.f), 1.f);
    g_iy[id]   = sqrtf(fmaf(r, r, fmaf(g, g, fmaf(b, b, 1e-6f))));
    float lr = logf(r + 1e-6f);
    float lg = logf(g + 1e-6f);
    float lb = logf(b + 1e-6f);
    g_a   [id] = lr - lg;
    g_bdif[id] = lr - lb;
}

// -------------------------------------------------------------------- k2 ---
// 288 CTAs x 256 threads. CTA = (unit = bid%24, chunk = bid/24).
// Double-buffered 64-px tiles; eval(tl) || mma(tl-1); warp-tile 32x64
// (4 M-groups x 2 N-groups) to cut redundant B ldmatrix traffic.
__global__ void __launch_bounds__(256, 2) k2_hist() {
    extern __shared__ char dyn[];
    const int bid   = blockIdx.x;
    const int unit  = bid % NUNITS;
    const int chunk = bid / NUNITS;
    const int img   = unit / 12;
    const int bp    = unit % 12;
    const int bat   = bp / 3;
    const int pair  = bp % 3;
    const int off   = (img * NBATCH + bat) * NPIX;

    float cua, cub, cva, cvb;
    if      (pair == 0) { cua =  1.f; cub =  0.f; cva =  0.f; cvb =  1.f; }
    else if (pair == 1) { cua = -1.f; cub =  0.f; cva = -1.f; cvb =  1.f; }
    else                { cua =  0.f; cub = -1.f; cva =  1.f; cvb = -1.f; }

    const int t    = threadIdx.x;
    const int wid  = t >> 5;
    const int lane = t & 31;

    float* stage = (float*)(dyn + STAGE_OFF);   // [4][3][64] : u, v, iy

    float acc[2][8][4];
#pragma unroll
    for (int mi = 0; mi < 2; mi++)
#pragma unroll
        for (int j = 0; j < 8; j++)
#pragma unroll
            for (int q = 0; q < 4; q++) acc[mi][j][q] = 0.f;

    // eval role
    const int   r    = t & 127;
    const bool  isA  = t < 128;
    const float mus  = (-3.0f + (float)r * (6.0f / 127.0f)) * 50.0f;
    const u64t  nmus2 = pack2(-mus, -mus);
    const u64t  one2  = pack2(1.0f, 1.0f);
    const int   prot = (r >> 3) & 3;            // conflict-free word rotation
    char* rowp = dyn + (isA ? 0 : TILE_BYTES) + r * (2 * PITCH);

    // mma role: warp = (g = wid&3 -> M rows g*32..+31, h = wid>>2 -> N cols h*64..+63)
    const int g = wid & 3;
    const int h = wid >> 2;
    const uint32_t sbase = smem_u32(dyn);
    const uint32_t aAddr = sbase + (g*32 + (lane & 15))*2*PITCH + (lane >> 4)*16;
    const uint32_t bAddr = sbase + TILE_BYTES
                         + (h*64 + (lane & 15))*2*PITCH + (lane >> 4)*16;

    const int start  = chunk * CHUNK_PX;
    const int end    = min(start + CHUNK_PX, NPIX);
    const int ntiles = (end - start) / KT;       // 86 or 78, exact

    // prologue: stage px(0), px(1)
    if (t < 128) {
        const int tl0 = t >> 6, i = t & 63;
        float* st = stage + (tl0 & 3) * 192;
        const int gi = off + start + tl0 * KT + i;
        float av = g_a[gi], bv = g_bdif[gi];
        st[i]       = fmaf(cua, av, cub * bv) * 50.0f;
        st[64 + i]  = fmaf(cva, av, cvb * bv) * 50.0f;
        st[128 + i] = g_iy[gi];
    }
    __syncthreads();

    for (int tl = 0; tl < ntiles; ++tl) {
        // ---- eval(tl) into buf[tl&1] ----
        {
            const float* st = stage + (tl & 3) * 192;
            const float* xs = st + (isA ? 0 : 64);
            const float* iy = st + 128;
            char* tile = rowp + (tl & 1) * BUF_BYTES;
#pragma unroll 8
            for (int pp = 0; pp < 32; ++pp) {
                const int p2 = (pp + prot) & 31;
                u64t xp = *(const u64t*)(xs + 2 * p2);      // LDS.64 pixel pair
                u64t dd, qq2;
                asm("add.rn.f32x2 %0, %1, %2;" : "=l"(dd)  : "l"(xp), "l"(nmus2));
                asm("fma.rn.f32x2 %0, %1, %1, %2;" : "=l"(qq2) : "l"(dd), "l"(one2));
                float q0, q1;
                asm("mov.b64 {%0, %1}, %2;" : "=f"(q0), "=f"(q1) : "l"(qq2));
                float qq = q0 * q1, rr;
                asm("rcp.approx.ftz.f32 %0, %1;" : "=f"(rr) : "f"(qq));
                float k0 = rr * q1, k1 = rr * q0;
                if (isA) {
                    float2 iy2 = *(const float2*)(iy + 2 * p2);
                    k0 *= iy2.x; k1 *= iy2.y;
                }
                uint32_t pk;   // lo = even px, hi = odd px
                asm("cvt.rn.satfinite.bf16x2.f32 %0, %1, %2;" : "=r"(pk) : "f"(k1), "f"(k0));
                *(uint32_t*)(tile + p2 * 4) = pk;
            }
        }

        // ---- mma(tl-1) on buf[(tl-1)&1] ----
        if (tl > 0) {
            const uint32_t bo = ((tl - 1) & 1) * BUF_BYTES;
#pragma unroll
            for (int kk = 0; kk < 4; ++kk) {
                uint32_t a0, a1, a2, a3, a4, a5, a6, a7;
                ldm_x4(a0, a1, a2, a3, aAddr + bo + kk * 32);
                ldm_x4(a4, a5, a6, a7, aAddr + bo + kk * 32 + 16 * 2 * PITCH);
#pragma unroll
                for (int j2 = 0; j2 < 4; ++j2) {
                    uint32_t b0, b1, b2, b3;
                    ldm_x4(b0, b1, b2, b3, bAddr + bo + kk * 32
                                          + j2 * 16 * 2 * PITCH);
                    mma16816(acc[0][2*j2    ], a0, a1, a2, a3, b0, b2);
                    mma16816(acc[0][2*j2 + 1], a0, a1, a2, a3, b1, b3);
                    mma16816(acc[1][2*j2    ], a4, a5, a6, a7, b0, b2);
                    mma16816(acc[1][2*j2 + 1], a4, a5, a6, a7, b1, b3);
                }
            }
        }

        // ---- prefetch px(tl+2) ----
        if (t < 64 && tl + 2 < ntiles) {
            float* st = stage + ((tl + 2) & 3) * 192;
            const int gi = off + start + (tl + 2) * KT + t;
            float av = g_a[gi], bv = g_bdif[gi];
            st[t]       = fmaf(cua, av, cub * bv) * 50.0f;
            st[64 + t]  = fmaf(cva, av, cvb * bv) * 50.0f;
            st[128 + t] = g_iy[gi];
        }
        __syncthreads();
    }

    // ---- final mma(ntiles-1) ----
    {
        const uint32_t bo = ((ntiles - 1) & 1) * BUF_BYTES;
#pragma unroll
        for (int kk = 0; kk < 4; ++kk) {
            uint32_t a0, a1, a2, a3, a4, a5, a6, a7;
            ldm_x4(a0, a1, a2, a3, aAddr + bo + kk * 32);
            ldm_x4(a4, a5, a6, a7, aAddr + bo + kk * 32 + 16 * 2 * PITCH);
#pragma unroll
            for (int j2 = 0; j2 < 4; ++j2) {
                uint32_t b0, b1, b2, b3;
                ldm_x4(b0, b1, b2, b3, bAddr + bo + kk * 32
                                      + j2 * 16 * 2 * PITCH);
                mma16816(acc[0][2*j2    ], a0, a1, a2, a3, b0, b2);
                mma16816(acc[0][2*j2 + 1], a0, a1, a2, a3, b1, b3);
                mma16816(acc[1][2*j2    ], a4, a5, a6, a7, b0, b2);
                mma16816(acc[1][2*j2 + 1], a4, a5, a6, a7, b1, b3);
            }
        }
    }

    // Epilogue: fragment-indexed stores.
    float* outp = g_partial + (unit * NCHUNK + chunk) * CELLS;
    const int cofs = 2 * (lane & 3);
#pragma unroll
    for (int mi = 0; mi < 2; ++mi) {
        const int row0 = g * 32 + mi * 16 + (lane >> 2);
#pragma unroll
        for (int j2 = 0; j2 < 4; ++j2)
#pragma unroll
            for (int hh = 0; hh < 2; ++hh) {
                const int c = h * 64 + 16 * j2 + 8 * hh + cofs;
                float* a4 = acc[mi][2 * j2 + hh];
                *(float2*)(outp +  row0      * HB + c) = make_float2(a4[0], a4[1]);
                *(float2*)(outp + (row0 + 8) * HB + c) = make_float2(a4[2], a4[3]);
            }
    }
}

// -------------------------------------------------------------------- k3 ---
// 768 blocks: bp = blk>>6 (batch*3+pair), seg = blk&63. Fused Hellinger
// partials: block sums of p, t, sqrt(p*t).
__global__ void k3_reduce() {
    int blk  = blockIdx.x;
    int bp   = blk >> 6;
    int seg  = blk & 63;
    int cell = seg * 256 + threadIdx.x;
    float p = 0.f, tt = 0.f;
#pragma unroll
    for (int c = 0; c < NCHUNK; c++) {
        p  += g_partial[((bp     ) * NCHUNK + c) * CELLS + cell];
        tt += g_partial[((12 + bp) * NCHUNK + c) * CELLS + cell];
    }
    float s = sqrtf(p * tt);

    __shared__ float redp[8], redt[8], reds[8];
#pragma unroll
    for (int o = 16; o > 0; o >>= 1) {
        p  += __shfl_down_sync(0xffffffffu, p,  o);
        tt += __shfl_down_sync(0xffffffffu, tt, o);
        s  += __shfl_down_sync(0xffffffffu, s,  o);
    }
    if ((threadIdx.x & 31) == 0) {
        redp[threadIdx.x >> 5] = p;
        redt[threadIdx.x >> 5] = tt;
        reds[threadIdx.x >> 5] = s;
    }
    __syncthreads();
    if (threadIdx.x == 0) {
        float sp = 0.f, st = 0.f, ss = 0.f;
#pragma unroll
        for (int w = 0; w < 8; w++) { sp += redp[w]; st += redt[w]; ss += reds[w]; }
        g_bsp[blk] = sp; g_bst[blk] = st; g_bss[blk] = ss;
    }
}

// ---------------------------------------------------------------- k4final ---
__global__ void k4_final(float* out) {
    int w = threadIdx.x >> 5, lane = threadIdx.x & 31;
    __shared__ float sl[4];
    if (w < 4) {
        float sp = 0.f, st = 0.f, ss = 0.f;
        for (int i = lane; i < 192; i += 32) {
            int blk = (3 * w) * 64 + i;
            sp += g_bsp[blk]; st += g_bst[blk]; ss += g_bss[blk];
        }
#pragma unroll
        for (int o = 16; o > 0; o >>= 1) {
            sp += __shfl_down_sync(0xffffffffu, sp, o);
            st += __shfl_down_sync(0xffffffffu, st, o);
            ss += __shfl_down_sync(0xffffffffu, ss, o);
        }
        if (lane == 0) {
            float Np = sp + 1e-6f, Nt = st + 1e-6f;
            sl[w] = sp / Np + st / Nt - 2.f * ss / sqrtf(Np * Nt);
        }
    }
    __syncthreads();
    if (threadIdx.x == 0) {
        float tot = fmaxf(sl[0] + sl[1] + sl[2] + sl[3], 0.f);
        out[0] = sqrtf(tot) * 0.70710678118654752f * 0.25f;  // (1/sqrt2)/B
    }
}

// ---------------------------------------------------------------------------
extern "C" void kernel_launch(void* const* d_in, const int* in_sizes, int n_in,
                              void* d_out, int out_size) {
    const float* pred = (const float*)d_in[0];
    const float* tgt  = (const float*)d_in[1];
    float* out = (float*)d_out;

    cudaFuncSetAttribute(k2_hist, cudaFuncAttributeMaxDynamicSharedMemorySize,
                         SMEM_TOTAL);

    k1_prep <<<2048, 256>>>(pred, tgt);
    k2_hist <<<NUNITS * NCHUNK, 256, SMEM_TOTAL>>>();
    k3_reduce<<<12 * 64, 256>>>();
    k4_final<<<1, 128>>>(out);
}

// round 8
// speedup vs baseline: 6.0186x; 1.2264x over previous
#include <cuda_runtime.h>
#include <cuda_bf16.h>
#include <math.h>
#include <stdint.h>

// ---------------------------------------------------------------------------
// HistLoss: RGB-uv histogram Hellinger loss. (Round 8: STS.128 eval stores,
// LDS.128 pixel loads, 4-way shared RCP, balanced prefetch, ncu reorder)
// ---------------------------------------------------------------------------

#define NPIX    65536
#define HB      128
#define CELLS   (HB*HB)
#define NBATCH  4
#define NUNITS  24
#define NCHUNK  12
#define CHUNK_PX 5504       // 86*64; chunk 11 gets 4992 = 78*64 (all full tiles)
#define KT      64          // pixels per staged tile
#define PITCH   72          // halves per smem row (144 B = 9*16B, conflict-free)
#define TILE_BYTES (HB*PITCH*2)       // 18432
#define BUF_BYTES  (2*TILE_BYTES)     // 36864 (A+B)
#define STAGE_OFF  (2*BUF_BYTES)      // 73728
#define SMEM_TOTAL (STAGE_OFF + 4*192*4)   // 76800

typedef unsigned long long u64t;

static __device__ float g_a      [2*NBATCH*NPIX];
static __device__ float g_bdif   [2*NBATCH*NPIX];
static __device__ float g_iy     [2*NBATCH*NPIX];
static __device__ float g_partial[NUNITS*NCHUNK*CELLS];   // ~18.9 MB
static __device__ float g_bsp[12*64];
static __device__ float g_bst[12*64];
static __device__ float g_bss[12*64];

__device__ __forceinline__ uint32_t smem_u32(const void* p) {
    uint32_t a;
    asm("{ .reg .u64 t; cvta.to.shared.u64 t, %1; cvt.u32.u64 %0, t; }"
        : "=r"(a) : "l"(p));
    return a;
}
__device__ __forceinline__ u64t pack2(float lo, float hi) {
    u64t r; asm("mov.b64 %0, {%1, %2};" : "=l"(r) : "f"(lo), "f"(hi)); return r;
}
__device__ __forceinline__ u64t add2(u64t a, u64t b) {
    u64t d; asm("add.rn.f32x2 %0, %1, %2;" : "=l"(d) : "l"(a), "l"(b)); return d;
}
__device__ __forceinline__ u64t fma2_sq1(u64t a, u64t c) {   // a*a + c
    u64t d; asm("fma.rn.f32x2 %0, %1, %1, %2;" : "=l"(d) : "l"(a), "l"(c)); return d;
}
__device__ __forceinline__ void unpk(u64t v, float& lo, float& hi) {
    asm("mov.b64 {%0, %1}, %2;" : "=f"(lo), "=f"(hi) : "l"(v));
}
__device__ __forceinline__ void lds_2x64(u64t& a, u64t& b, uint32_t addr) {
    asm volatile("ld.shared.v2.b64 {%0, %1}, [%2];" : "=l"(a), "=l"(b) : "r"(addr));
}
__device__ __forceinline__ void ldm_x4(uint32_t& r0, uint32_t& r1,
                                       uint32_t& r2, uint32_t& r3, uint32_t a) {
    asm volatile("ldmatrix.sync.aligned.m8n8.x4.shared.b16 {%0,%1,%2,%3}, [%4];"
                 : "=r"(r0), "=r"(r1), "=r"(r2), "=r"(r3) : "r"(a));
}
__device__ __forceinline__ void mma16816(float* d, uint32_t a0, uint32_t a1,
                                         uint32_t a2, uint32_t a3,
                                         uint32_t b0, uint32_t b1) {
    asm volatile(
        "mma.sync.aligned.m16n8k16.row.col.f32.bf16.bf16.f32 "
        "{%0,%1,%2,%3}, {%4,%5,%6,%7}, {%8,%9}, {%0,%1,%2,%3};"
        : "+f"(d[0]), "+f"(d[1]), "+f"(d[2]), "+f"(d[3])
        : "r"(a0), "r"(a1), "r"(a2), "r"(a3), "r"(b0), "r"(b1));
}

// -------------------------------------------------------------------- k1 ---
__global__ void k1_prep(const float* __restrict__ pred,
                        const float* __restrict__ tgt) {
    int id  = blockIdx.x * blockDim.x + threadIdx.x;      // 524288 threads
    int img = id >> 18;
    int rem = id & ((1 << 18) - 1);
    int bat = rem >> 16;
    int n   = rem & (NPIX - 1);
    const float* src = (img ? tgt : pred) + bat * 3 * NPIX;
    float r = fminf(fmaxf(src[n          ], 0.f), 1.f);
    float g = fminf(fmaxf(src[n +   NPIX ], 0.f), 1.f);
    float b = fminf(fmaxf(src[n + 2*NPIX ], 0.f), 1.f);
    g_iy[id]   = sqrtf(fmaf(r, r, fmaf(g, g, fmaf(b, b, 1e-6f))));
    float lr = logf(r + 1e-6f);
    float lg = logf(g + 1e-6f);
    float lb = logf(b + 1e-6f);
    g_a   [id] = lr - lg;
    g_bdif[id] = lr - lb;
}

// nop kernels: position k2_hist at profiled launch index 3
__global__ void k_nop() {}

// -------------------------------------------------------------------- k2 ---
// 288 CTAs x 256 threads. CTA = (unit = bid%24, chunk = bid/24).
// Double-buffered 64-px tiles; eval(tl) || mma(tl-1); warp-tile 32x64.
// Eval: per 8 px: 2x LDS.128 -> f32x2 d/q -> 4-way shared rcp -> STS.128.
__global__ void __launch_bounds__(256, 2) k2_hist() {
    extern __shared__ char dyn[];
    const int bid   = blockIdx.x;
    const int unit  = bid % NUNITS;
    const int chunk = bid / NUNITS;
    const int img   = unit / 12;
    const int bp    = unit % 12;
    const int bat   = bp / 3;
    const int pair  = bp % 3;
    const int off   = (img * NBATCH + bat) * NPIX;

    float cua, cub, cva, cvb;
    if      (pair == 0) { cua =  1.f; cub =  0.f; cva =  0.f; cvb =  1.f; }
    else if (pair == 1) { cua = -1.f; cub =  0.f; cva = -1.f; cvb =  1.f; }
    else                { cua =  0.f; cub = -1.f; cva =  1.f; cvb = -1.f; }

    const int t    = threadIdx.x;
    const int wid  = t >> 5;
    const int lane = t & 31;

    const uint32_t sbase    = smem_u32(dyn);
    const uint32_t stageAdr = sbase + STAGE_OFF;
    float* stage = (float*)(dyn + STAGE_OFF);   // [4][3][64] : u, v, iy

    float acc[2][8][4];
#pragma unroll
    for (int mi = 0; mi < 2; mi++)
#pragma unroll
        for (int j = 0; j < 8; j++)
#pragma unroll
            for (int q = 0; q < 4; q++) acc[mi][j][q] = 0.f;

    // eval role: thread owns bin-row r of A (t<128) or B (t>=128)
    const int   r    = t & 127;
    const bool  isA  = t < 128;
    const float mus  = (-3.0f + (float)r * (6.0f / 127.0f)) * 50.0f;
    const u64t  nmus2 = pack2(-mus, -mus);
    const u64t  one2  = pack2(1.0f, 1.0f);
    const uint32_t rowAdr = sbase + (isA ? 0 : TILE_BYTES) + r * (2 * PITCH);

    // mma role: warp (g = wid&3 -> rows g*32.., h = wid>>2 -> cols h*64..)
    const int g = wid & 3;
    const int h = wid >> 2;
    const uint32_t aAddr = sbase + (g*32 + (lane & 15))*2*PITCH + (lane >> 4)*16;
    const uint32_t bAddr = sbase + TILE_BYTES
                         + (h*64 + (lane & 15))*2*PITCH + (lane >> 4)*16;

    const int start  = chunk * CHUNK_PX;
    const int end    = min(start + CHUNK_PX, NPIX);
    const int ntiles = (end - start) / KT;       // 86 or 78, exact

    // prologue: stage px(0), px(1)
    if (t < 128) {
        const int tl0 = t >> 6, i = t & 63;
        float* st = stage + (tl0 & 3) * 192;
        const int gi = off + start + tl0 * KT + i;
        float av = g_a[gi], bv = g_bdif[gi];
        st[i]       = fmaf(cua, av, cub * bv) * 50.0f;
        st[64 + i]  = fmaf(cva, av, cvb * bv) * 50.0f;
        st[128 + i] = g_iy[gi];
    }
    __syncthreads();

    for (int tl = 0; tl < ntiles; ++tl) {
        // ---- eval(tl) into buf[tl&1] ----
        {
            const uint32_t slot = stageAdr + (tl & 3) * 768;
            const uint32_t xsA  = slot + (isA ? 0 : 256);
            const uint32_t iyA  = slot + 512;
            const uint32_t dstA = rowAdr + (tl & 1) * BUF_BYTES;
#pragma unroll
            for (int pp = 0; pp < 8; ++pp) {
                u64t xpa, xpb;
                lds_2x64(xpa, xpb, xsA + pp * 32);
                uint32_t pk0, pk1, pk2, pk3;
                // group a: px 8pp..8pp+3
                {
                    u64t qqa = fma2_sq1(add2(xpa, nmus2), one2);
                    u64t qqb = fma2_sq1(add2(xpb, nmus2), one2);
                    float q0, q1, q2, q3;
                    unpk(qqa, q0, q1); unpk(qqb, q2, q3);
                    float q01 = q0 * q1, q23 = q2 * q3, Q = q01 * q23, rr;
                    asm("rcp.approx.ftz.f32 %0, %1;" : "=f"(rr) : "f"(Q));
                    float r01 = rr * q23, r23 = rr * q01;
                    float k0 = r01 * q1, k1 = r01 * q0;
                    float k2 = r23 * q3, k3 = r23 * q2;
                    if (isA) {
                        float4 w = *(const float4*)(dyn + (iyA - sbase) + pp * 32);
                        k0 *= w.x; k1 *= w.y; k2 *= w.z; k3 *= w.w;
                    }
                    asm("cvt.rn.satfinite.bf16x2.f32 %0, %1, %2;" : "=r"(pk0) : "f"(k1), "f"(k0));
                    asm("cvt.rn.satfinite.bf16x2.f32 %0, %1, %2;" : "=r"(pk1) : "f"(k3), "f"(k2));
                }
                // group b: px 8pp+4..8pp+7
                {
                    u64t xpc, xpd;
                    lds_2x64(xpc, xpd, xsA + pp * 32 + 16);
                    u64t qqa = fma2_sq1(add2(xpc, nmus2), one2);
                    u64t qqb = fma2_sq1(add2(xpd, nmus2), one2);
                    float q0, q1, q2, q3;
                    unpk(qqa, q0, q1); unpk(qqb, q2, q3);
                    float q01 = q0 * q1, q23 = q2 * q3, Q = q01 * q23, rr;
                    asm("rcp.approx.ftz.f32 %0, %1;" : "=f"(rr) : "f"(Q));
                    float r01 = rr * q23, r23 = rr * q01;
                    float k0 = r01 * q1, k1 = r01 * q0;
                    float k2 = r23 * q3, k3 = r23 * q2;
                    if (isA) {
                        float4 w = *(const float4*)(dyn + (iyA - sbase) + pp * 32 + 16);
                        k0 *= w.x; k1 *= w.y; k2 *= w.z; k3 *= w.w;
                    }
                    asm("cvt.rn.satfinite.bf16x2.f32 %0, %1, %2;" : "=r"(pk2) : "f"(k1), "f"(k0));
                    asm("cvt.rn.satfinite.bf16x2.f32 %0, %1, %2;" : "=r"(pk3) : "f"(k3), "f"(k2));
                }
                asm volatile("st.shared.v4.b32 [%0], {%1,%2,%3,%4};"
                             :: "r"(dstA + pp * 16),
                                "r"(pk0), "r"(pk1), "r"(pk2), "r"(pk3) : "memory");
            }
        }

        // ---- mma(tl-1) on buf[(tl-1)&1] ----
        if (tl > 0) {
            const uint32_t bo = ((tl - 1) & 1) * BUF_BYTES;
#pragma unroll
            for (int kk = 0; kk < 4; ++kk) {
                uint32_t a0, a1, a2, a3, a4, a5, a6, a7;
                ldm_x4(a0, a1, a2, a3, aAddr + bo + kk * 32);
                ldm_x4(a4, a5, a6, a7, aAddr + bo + kk * 32 + 16 * 2 * PITCH);
#pragma unroll
                for (int j2 = 0; j2 < 4; ++j2) {
                    uint32_t b0, b1, b2, b3;
                    ldm_x4(b0, b1, b2, b3, bAddr + bo + kk * 32
                                          + j2 * 16 * 2 * PITCH);
                    mma16816(acc[0][2*j2    ], a0, a1, a2, a3, b0, b2);
                    mma16816(acc[0][2*j2 + 1], a0, a1, a2, a3, b1, b3);
                    mma16816(acc[1][2*j2    ], a4, a5, a6, a7, b0, b2);
                    mma16816(acc[1][2*j2 + 1], a4, a5, a6, a7, b1, b3);
                }
            }
        }

        // ---- prefetch px(tl+2) (warps 6-7: B-role, lighter eval) ----
        if (t >= 192 && tl + 2 < ntiles) {
            const int i = t - 192;
            float* st = stage + ((tl + 2) & 3) * 192;
            const int gi = off + start + (tl + 2) * KT + i;
            float av = g_a[gi], bv = g_bdif[gi];
            st[i]       = fmaf(cua, av, cub * bv) * 50.0f;
            st[64 + i]  = fmaf(cva, av, cvb * bv) * 50.0f;
            st[128 + i] = g_iy[gi];
        }
        __syncthreads();
    }

    // ---- final mma(ntiles-1) ----
    {
        const uint32_t bo = ((ntiles - 1) & 1) * BUF_BYTES;
#pragma unroll
        for (int kk = 0; kk < 4; ++kk) {
            uint32_t a0, a1, a2, a3, a4, a5, a6, a7;
            ldm_x4(a0, a1, a2, a3, aAddr + bo + kk * 32);
            ldm_x4(a4, a5, a6, a7, aAddr + bo + kk * 32 + 16 * 2 * PITCH);
#pragma unroll
            for (int j2 = 0; j2 < 4; ++j2) {
                uint32_t b0, b1, b2, b3;
                ldm_x4(b0, b1, b2, b3, bAddr + bo + kk * 32
                                      + j2 * 16 * 2 * PITCH);
                mma16816(acc[0][2*j2    ], a0, a1, a2, a3, b0, b2);
                mma16816(acc[0][2*j2 + 1], a0, a1, a2, a3, b1, b3);
                mma16816(acc[1][2*j2    ], a4, a5, a6, a7, b0, b2);
                mma16816(acc[1][2*j2 + 1], a4, a5, a6, a7, b1, b3);
            }
        }
    }

    // Epilogue: fragment-indexed stores.
    float* outp = g_partial + (unit * NCHUNK + chunk) * CELLS;
    const int cofs = 2 * (lane & 3);
#pragma unroll
    for (int mi = 0; mi < 2; ++mi) {
        const int row0 = g * 32 + mi * 16 + (lane >> 2);
#pragma unroll
        for (int j2 = 0; j2 < 4; ++j2)
#pragma unroll
            for (int hh = 0; hh < 2; ++hh) {
                const int c = h * 64 + 16 * j2 + 8 * hh + cofs;
                float* a4 = acc[mi][2 * j2 + hh];
                *(float2*)(outp +  row0      * HB + c) = make_float2(a4[0], a4[1]);
                *(float2*)(outp + (row0 + 8) * HB + c) = make_float2(a4[2], a4[3]);
            }
    }
}

// -------------------------------------------------------------------- k3 ---
__global__ void k3_reduce() {
    int blk  = blockIdx.x;
    int bp   = blk >> 6;
    int seg  = blk & 63;
    int cell = seg * 256 + threadIdx.x;
    float p = 0.f, tt = 0.f;
#pragma unroll
    for (int c = 0; c < NCHUNK; c++) {
        p  += g_partial[((bp     ) * NCHUNK + c) * CELLS + cell];
        tt += g_partial[((12 + bp) * NCHUNK + c) * CELLS + cell];
    }
    float s = sqrtf(p * tt);

    __shared__ float redp[8], redt[8], reds[8];
#pragma unroll
    for (int o = 16; o > 0; o >>= 1) {
        p  += __shfl_down_sync(0xffffffffu, p,  o);
        tt += __shfl_down_sync(0xffffffffu, tt, o);
        s  += __shfl_down_sync(0xffffffffu, s,  o);
    }
    if ((threadIdx.x & 31) == 0) {
        redp[threadIdx.x >> 5] = p;
        redt[threadIdx.x >> 5] = tt;
        reds[threadIdx.x >> 5] = s;
    }
    __syncthreads();
    if (threadIdx.x == 0) {
        float sp = 0.f, st = 0.f, ss = 0.f;
#pragma unroll
        for (int w = 0; w < 8; w++) { sp += redp[w]; st += redt[w]; ss += reds[w]; }
        g_bsp[blk] = sp; g_bst[blk] = st; g_bss[blk] = ss;
    }
}

// ---------------------------------------------------------------- k4final ---
__global__ void k4_final(float* out) {
    int w = threadIdx.x >> 5, lane = threadIdx.x & 31;
    __shared__ float sl[4];
    if (w < 4) {
        float sp = 0.f, st = 0.f, ss = 0.f;
        for (int i = lane; i < 192; i += 32) {
            int blk = (3 * w) * 64 + i;
            sp += g_bsp[blk]; st += g_bst[blk]; ss += g_bss[blk];
        }
#pragma unroll
        for (int o = 16; o > 0; o >>= 1) {
            sp += __shfl_down_sync(0xffffffffu, sp, o);
            st += __shfl_down_sync(0xffffffffu, st, o);
            ss += __shfl_down_sync(0xffffffffu, ss, o);
        }
        if (lane == 0) {
            float Np = sp + 1e-6f, Nt = st + 1e-6f;
            sl[w] = sp / Np + st / Nt - 2.f * ss / sqrtf(Np * Nt);
        }
    }
    __syncthreads();
    if (threadIdx.x == 0) {
        float tot = fmaxf(sl[0] + sl[1] + sl[2] + sl[3], 0.f);
        out[0] = sqrtf(tot) * 0.70710678118654752f * 0.25f;  // (1/sqrt2)/B
    }
}

// ---------------------------------------------------------------------------
extern "C" void kernel_launch(void* const* d_in, const int* in_sizes, int n_in,
                              void* d_out, int out_size) {
    const float* pred = (const float*)d_in[0];
    const float* tgt  = (const float*)d_in[1];
    float* out = (float*)d_out;

    cudaFuncSetAttribute(k2_hist, cudaFuncAttributeMaxDynamicSharedMemorySize,
                         SMEM_TOTAL);

    k1_prep <<<2048, 256>>>(pred, tgt);
    k_nop   <<<1, 32>>>();       // positions k2_hist at profiled launch idx 3
    k_nop   <<<1, 32>>>();
    k2_hist <<<NUNITS * NCHUNK, 256, SMEM_TOTAL>>>();
    k3_reduce<<<12 * 64, 256>>>();
    k4_final<<<1, 128>>>(out);
}